// round 4
// baseline (speedup 1.0000x reference)
#include <cuda_runtime.h>
#include <cstdint>

#define NNODES 100000
#define NEDGES 800000
#define DIM    128

// ---------------- scratch (static device globals; no allocation allowed) ----
__device__ float g_sum_in [(size_t)NNODES * DIM];
__device__ float g_sum_out[(size_t)NNODES * DIM];
__device__ int   g_cnt_in [NNODES];
__device__ int   g_cnt_out[NNODES];
__device__ int   g_is64;          // 1 if edge_index is int64, 0 if int32

// ---------------- small PTX helpers ----------------------------------------
__device__ __forceinline__ void red_add_v4(float* addr, float4 v) {
    asm volatile("red.global.add.v4.f32 [%0], {%1, %2, %3, %4};"
                 :: "l"(addr), "f"(v.x), "f"(v.y), "f"(v.z), "f"(v.w)
                 : "memory");
}

__device__ __forceinline__ unsigned long long pack2(float lo, float hi) {
    unsigned long long r;
    asm("mov.b64 %0, {%1, %2};" : "=l"(r) : "f"(lo), "f"(hi));
    return r;
}
__device__ __forceinline__ unsigned long long dup2(float v) {
    unsigned long long r;
    asm("mov.b64 %0, {%1, %1};" : "=l"(r) : "f"(v));
    return r;
}
__device__ __forceinline__ void fma2(unsigned long long& d,
                                     unsigned long long a,
                                     unsigned long long b) {
    asm("fma.rn.f32x2 %0, %1, %2, %3;" : "=l"(d) : "l"(a), "l"(b), "l"(d));
}
__device__ __forceinline__ void unpack2(unsigned long long v, float& lo, float& hi) {
    asm("mov.b64 {%0, %1}, %2;" : "=f"(lo), "=f"(hi) : "l"(v));
}

// ---------------- kernel 0: edge dtype detection ----------------------------
__global__ void detect_kernel(const void* ei, int nedges, int nnodes)
{
    // If the first 64 values, interpreted as int64, are all valid node ids,
    // treat as int64. int32 data read as int64 packs two indices per word ->
    // values >= 2^32 whenever the odd-position index != 0 (overwhelmingly
    // likely across 64 random samples).
    const long long* p = (const long long*)ei;
    int m = nedges < 64 ? nedges : 64;
    int ok = 1;
    for (int i = 0; i < m; i++) {
        long long v = p[i];
        if (v < 0 || v >= nnodes) { ok = 0; break; }
    }
    g_is64 = ok;
}

// ---------------- kernel 1: edge aggregation (warp per edge) ---------------
__global__ __launch_bounds__(256)
void agg_kernel(const float* __restrict__ x,
                const void* __restrict__ ei,
                float* __restrict__ sum_in, float* __restrict__ sum_out,
                int* __restrict__ cnt_in, int* __restrict__ cnt_out,
                int nedges, int nnodes)
{
    int warp = (blockIdx.x * blockDim.x + threadIdx.x) >> 5;
    int lane = threadIdx.x & 31;
    if (warp >= nedges) return;

    long long s64, d64;
    if (g_is64) {
        const long long* p = (const long long*)ei;
        s64 = p[warp];
        d64 = p[nedges + warp];
    } else {
        const int* p = (const int*)ei;
        s64 = p[warp];
        d64 = p[nedges + warp];
    }
    if (s64 < 0 || s64 >= nnodes || d64 < 0 || d64 >= nnodes) return;
    int src = (int)s64;
    int dst = (int)d64;

    const float4 xs = *(const float4*)(x + (size_t)src * DIM + lane * 4);
    const float4 xd = *(const float4*)(x + (size_t)dst * DIM + lane * 4);

    // flow source_to_target: aggregate src features at dst
    red_add_v4(sum_in  + (size_t)dst * DIM + lane * 4, xs);
    // flow target_to_source: aggregate dst features at src
    red_add_v4(sum_out + (size_t)src * DIM + lane * 4, xd);

    if (lane == 0) {
        atomicAdd(cnt_in  + dst, 1);
        atomicAdd(cnt_out + src, 1);
    }
}

// ---------------- kernel 2: fused GEMM  out = [x|a_in|a_out] @ W_cat + bias -
#define MT 64          // rows per block
#define KT 32          // k-chunk
#define AST 68         // padded stride for transposed A tile (mult of 4)

__global__ __launch_bounds__(256)
void gemm_kernel(const float* __restrict__ x,
                 const float* __restrict__ Wself, const float* __restrict__ bself,
                 const float* __restrict__ Ws2d,  const float* __restrict__ bs2d,
                 const float* __restrict__ Wd2s,  const float* __restrict__ bd2s,
                 const float* __restrict__ sum_in, const float* __restrict__ sum_out,
                 const int* __restrict__ cnt_in,  const int* __restrict__ cnt_out,
                 float* __restrict__ out, int n)
{
    __shared__ float As[KT * AST];     // transposed: As[k][row]
    __shared__ float Bs[KT * DIM];     // Bs[k][col]
    __shared__ float sc_in[MT], sc_out[MT], sbias[DIM];

    const int t    = threadIdx.x;
    const int row0 = blockIdx.x * MT;

    if (t < MT) {
        int g  = row0 + t;
        int ci = (g < n) ? cnt_in[g]  : 1;
        int co = (g < n) ? cnt_out[g] : 1;
        sc_in[t]  = 0.5f / (float)max(ci, 1);
        sc_out[t] = 0.5f / (float)max(co, 1);
    }
    if (t < DIM) sbias[t] = bself[t] + 0.5f * (bs2d[t] + bd2s[t]);

    const int c0 = (t & 31) * 4;   // 4 output cols
    const int r0 = (t >> 5) * 8;   // 8 output rows

    unsigned long long acc[8][2];
    #pragma unroll
    for (int i = 0; i < 8; i++) { acc[i][0] = 0ull; acc[i][1] = 0ull; }

    for (int kb = 0; kb < 3 * DIM; kb += KT) {
        __syncthreads();

        // ---- stage A tile (with per-row scaling for the aggregated halves)
        const float* src;
        const float* scp = nullptr;
        int koff;
        if (kb < DIM)            { src = x;       koff = kb;           }
        else if (kb < 2 * DIM)   { src = sum_in;  koff = kb - DIM;     scp = sc_in;  }
        else                     { src = sum_out; koff = kb - 2 * DIM; scp = sc_out; }

        #pragma unroll
        for (int i = 0; i < 2; i++) {
            int idx = t + i * 256;
            int r   = idx >> 3;
            int kv  = (idx & 7) * 4;
            int g   = row0 + r;
            float4 v = make_float4(0.f, 0.f, 0.f, 0.f);
            if (g < n) v = *(const float4*)(src + (size_t)g * DIM + koff + kv);
            float s = scp ? scp[r] : 1.0f;
            As[(kv + 0) * AST + r] = v.x * s;
            As[(kv + 1) * AST + r] = v.y * s;
            As[(kv + 2) * AST + r] = v.z * s;
            As[(kv + 3) * AST + r] = v.w * s;
        }

        // ---- stage B tile
        const float* wsrc = (kb < DIM) ? Wself : ((kb < 2 * DIM) ? Ws2d : Wd2s);
        #pragma unroll
        for (int i = 0; i < 4; i++) {
            int idx = t + i * 256;
            int kk  = idx >> 5;
            int cv  = (idx & 31) * 4;
            *(float4*)&Bs[kk * DIM + cv] =
                *(const float4*)(wsrc + (size_t)(koff + kk) * DIM + cv);
        }
        __syncthreads();

        // ---- compute: 16 f32x2 FMA per k
        #pragma unroll
        for (int kk = 0; kk < KT; kk++) {
            float4 a0 = *(float4*)&As[kk * AST + r0];
            float4 a1 = *(float4*)&As[kk * AST + r0 + 4];
            float4 b  = *(float4*)&Bs[kk * DIM + c0];
            unsigned long long b0 = pack2(b.x, b.y);
            unsigned long long b1 = pack2(b.z, b.w);
            float av[8] = {a0.x, a0.y, a0.z, a0.w, a1.x, a1.y, a1.z, a1.w};
            #pragma unroll
            for (int i = 0; i < 8; i++) {
                unsigned long long ad = dup2(av[i]);
                fma2(acc[i][0], ad, b0);
                fma2(acc[i][1], ad, b1);
            }
        }
    }

    // ---- epilogue
    float bx0 = sbias[c0], bx1 = sbias[c0 + 1], bx2 = sbias[c0 + 2], bx3 = sbias[c0 + 3];
    #pragma unroll
    for (int i = 0; i < 8; i++) {
        int g = row0 + r0 + i;
        if (g < n) {
            float lo0, hi0, lo1, hi1;
            unpack2(acc[i][0], lo0, hi0);
            unpack2(acc[i][1], lo1, hi1);
            float4 o;
            o.x = lo0 + bx0; o.y = hi0 + bx1; o.z = lo1 + bx2; o.w = hi1 + bx3;
            *(float4*)(out + (size_t)g * DIM + c0) = o;
        }
    }
}

// ---------------- launch ----------------------------------------------------
extern "C" void kernel_launch(void* const* d_in, const int* in_sizes, int n_in,
                              void* d_out, int out_size)
{
    // Identify inputs by element count (robust to metadata reordering):
    //   x          : N*DIM   = 12,800,000 floats
    //   edge_index : 2*E     =  1,600,000 ints (32- or 64-bit, detected on device)
    //   W_*        : DIM*DIM =     16,384 floats (3, relative order self,s2d,d2s)
    //   b_*        : DIM     =        128 floats (3, relative order self,s2d,d2s)
    const float* x     = nullptr;
    const void*  ei    = nullptr;
    const float* Ws[3] = {nullptr, nullptr, nullptr};
    const float* bs[3] = {nullptr, nullptr, nullptr};
    int nw = 0, nb = 0;
    long long x_elems = 0, ei_elems = 0;

    for (int i = 0; i < n_in; i++) {
        long long sz = in_sizes[i];
        if (sz > 4000000)            { x = (const float*)d_in[i];  x_elems  = sz; }
        else if (sz > 100000)        { ei = d_in[i]; ei_elems = sz; }
        else if (sz == DIM * DIM)    { if (nw < 3) Ws[nw++] = (const float*)d_in[i]; }
        else if (sz == DIM)          { if (nb < 3) bs[nb++] = (const float*)d_in[i]; }
    }
    if (!x || !ei || nw < 3 || nb < 3) return;

    const float *Wself = Ws[0], *Ws2d = Ws[1], *Wd2s = Ws[2];
    const float *bself = bs[0], *bs2d = bs[1], *bd2s = bs[2];
    float* out = (float*)d_out;

    int n = (int)(x_elems / DIM);    // 100000
    int e = (int)(ei_elems / 2);     // 800000

    void *p_si, *p_so, *p_ci, *p_co;
    cudaGetSymbolAddress(&p_si, g_sum_in);
    cudaGetSymbolAddress(&p_so, g_sum_out);
    cudaGetSymbolAddress(&p_ci, g_cnt_in);
    cudaGetSymbolAddress(&p_co, g_cnt_out);

    cudaMemsetAsync(p_si, 0, (size_t)n * DIM * sizeof(float), 0);
    cudaMemsetAsync(p_so, 0, (size_t)n * DIM * sizeof(float), 0);
    cudaMemsetAsync(p_ci, 0, (size_t)n * sizeof(int), 0);
    cudaMemsetAsync(p_co, 0, (size_t)n * sizeof(int), 0);

    detect_kernel<<<1, 1>>>(ei, e, n);

    int warps_per_block = 256 / 32;
    int agg_blocks = (e + warps_per_block - 1) / warps_per_block;
    agg_kernel<<<agg_blocks, 256>>>(x, ei,
                                    (float*)p_si, (float*)p_so,
                                    (int*)p_ci, (int*)p_co, e, n);

    int gemm_blocks = (n + MT - 1) / MT;
    gemm_kernel<<<gemm_blocks, 256>>>(x, Wself, bself, Ws2d, bs2d, Wd2s, bd2s,
                                      (const float*)p_si, (const float*)p_so,
                                      (const int*)p_ci, (const int*)p_co,
                                      out, n);
}

// round 7
// speedup vs baseline: 1.3886x; 1.3886x over previous
#include <cuda_runtime.h>
#include <cstdint>

#define NNODES 100000
#define DIM    128
#define KTOT   384
#define KC     32
#define NCHUNK 12

// ---------------- scratch ----------------------------------------------------
__device__ float g_sum_in [(size_t)NNODES * DIM];
__device__ float g_sum_out[(size_t)NNODES * DIM];
__device__ int   g_cnt_in [NNODES];
__device__ int   g_cnt_out[NNODES];
__device__ int   g_is64;
__device__ unsigned int g_wt[(size_t)KTOT * DIM];   // W_cat as tf32, [k][n]

// ---------------- PTX helpers ------------------------------------------------
__device__ __forceinline__ void red_add_v4(float* addr, float4 v) {
    asm volatile("red.global.add.v4.f32 [%0], {%1, %2, %3, %4};"
                 :: "l"(addr), "f"(v.x), "f"(v.y), "f"(v.z), "f"(v.w) : "memory");
}
__device__ __forceinline__ unsigned int f2tf32(float f) {
    unsigned int u;
    asm("cvt.rna.tf32.f32 %0, %1;" : "=r"(u) : "f"(f));
    return u;
}
__device__ __forceinline__ void mma_tf32(float* d, const unsigned* a, const unsigned* b) {
    asm volatile("mma.sync.aligned.m16n8k8.row.col.f32.tf32.tf32.f32 "
        "{%0,%1,%2,%3}, {%4,%5,%6,%7}, {%8,%9}, {%0,%1,%2,%3};"
        : "+f"(d[0]), "+f"(d[1]), "+f"(d[2]), "+f"(d[3])
        : "r"(a[0]), "r"(a[1]), "r"(a[2]), "r"(a[3]), "r"(b[0]), "r"(b[1]));
}

// ---------------- kernel 0a: edge dtype detection ---------------------------
__global__ void detect_kernel(const void* ei, int nedges, int nnodes)
{
    const long long* p = (const long long*)ei;
    int m = nedges < 64 ? nedges : 64;
    int ok = 1;
    for (int i = 0; i < m; i++) {
        long long v = p[i];
        if (v < 0 || v >= nnodes) { ok = 0; break; }
    }
    g_is64 = ok;
}

// ---------------- kernel 0b: W_cat -> tf32, [k][n] --------------------------
__global__ __launch_bounds__(256)
void wt_kernel(const float* __restrict__ Wself, const float* __restrict__ Ws2d,
               const float* __restrict__ Wd2s, unsigned int* __restrict__ wt)
{
    int idx = blockIdx.x * 256 + threadIdx.x;       // 49152 total
    if (idx >= KTOT * DIM) return;
    int k = idx >> 7;          // 0..383
    int nn = idx & 127;        // coalesced
    const float* W = (k < DIM) ? Wself : ((k < 2 * DIM) ? Ws2d : Wd2s);
    wt[idx] = f2tf32(W[(size_t)(k & 127) * DIM + nn]);
}

// ---------------- kernel 1: edge aggregation --------------------------------
__global__ __launch_bounds__(256)
void agg_kernel(const float* __restrict__ x, const void* __restrict__ ei,
                float* __restrict__ sum_in, float* __restrict__ sum_out,
                int* __restrict__ cnt_in, int* __restrict__ cnt_out,
                int nedges, int nnodes)
{
    int warp = (blockIdx.x * blockDim.x + threadIdx.x) >> 5;
    int lane = threadIdx.x & 31;
    if (warp >= nedges) return;

    long long s64, d64;
    if (g_is64) {
        const long long* p = (const long long*)ei;
        s64 = p[warp]; d64 = p[nedges + warp];
    } else {
        const int* p = (const int*)ei;
        s64 = p[warp]; d64 = p[nedges + warp];
    }
    if (s64 < 0 || s64 >= nnodes || d64 < 0 || d64 >= nnodes) return;
    int src = (int)s64, dst = (int)d64;

    const float4 xs = *(const float4*)(x + (size_t)src * DIM + lane * 4);
    const float4 xd = *(const float4*)(x + (size_t)dst * DIM + lane * 4);
    red_add_v4(sum_in  + (size_t)dst * DIM + lane * 4, xs);
    red_add_v4(sum_out + (size_t)src * DIM + lane * 4, xd);
    if (lane == 0) { atomicAdd(cnt_in + dst, 1); atomicAdd(cnt_out + src, 1); }
}

// ---------------- kernel 2: mma.sync tf32 GEMM ------------------------------
// CTA: 128 rows x 128 cols.  8 warps in 4(m) x 2(n): warp tile 32m x 64n.
// Per warp: 2 m16-tiles x 8 n8-tiles, k in steps of 8.
#define AP 36     // A smem row pitch (floats):  (4m + c) distinct banks
#define BP 136    // B smem row pitch (floats):  (8k + n) distinct banks

__global__ __launch_bounds__(256)
void gemm_kernel(const float* __restrict__ x,
                 const float* __restrict__ bself, const float* __restrict__ bs2d,
                 const float* __restrict__ bd2s,
                 const float* __restrict__ sum_in, const float* __restrict__ sum_out,
                 const int* __restrict__ cnt_in, const int* __restrict__ cnt_out,
                 const unsigned int* __restrict__ wt,
                 float* __restrict__ out, int n)
{
    __shared__ unsigned int As[128 * AP];    // tf32 bits, [m][k] pitch AP
    __shared__ unsigned int Bs[KC * BP];     // tf32 bits, [k][n] pitch BP
    __shared__ float sbias[DIM], scin[128], scout[128];

    const int t    = threadIdx.x;
    const int wid  = t >> 5;
    const int lane = t & 31;
    const int gid  = lane >> 2;      // group id 0..7
    const int tig  = lane & 3;       // thread in group 0..3
    const int row0 = blockIdx.x * 128;
    const int wm   = (wid & 3) * 32;        // warp m offset
    const int wn   = (wid >> 2) * 64;       // warp n offset

    if (t < 128) {
        sbias[t] = bself[t] + 0.5f * (bs2d[t] + bd2s[t]);
        int g = row0 + t;
        int ci = (g < n) ? cnt_in[g]  : 1;
        int co = (g < n) ? cnt_out[g] : 1;
        scin[t]  = 0.5f / (float)max(ci, 1);
        scout[t] = 0.5f / (float)max(co, 1);
    }

    float acc[2][8][4];
    #pragma unroll
    for (int i = 0; i < 2; i++)
        #pragma unroll
        for (int j = 0; j < 8; j++)
            #pragma unroll
            for (int q = 0; q < 4; q++) acc[i][j][q] = 0.f;

    for (int c = 0; c < NCHUNK; c++) {
        const int kb = c * KC;
        const float* src; const float* scp; int koff;
        if (kb < DIM)            { src = x;       scp = nullptr; koff = kb; }
        else if (kb < 2 * DIM)   { src = sum_in;  scp = scin;    koff = kb - DIM; }
        else                     { src = sum_out; scp = scout;   koff = kb - 2 * DIM; }

        __syncthreads();
        // ---- stage A: 128 rows x 32 k (scale + tf32 convert)
        #pragma unroll
        for (int i = 0; i < 4; i++) {
            int idx = t + i * 256;            // 0..1023
            int r   = idx >> 3;               // 0..127
            int kq  = (idx & 7) * 4;          // 0..28
            int g   = row0 + r;
            float4 v = make_float4(0.f, 0.f, 0.f, 0.f);
            if (g < n) v = *(const float4*)(src + (size_t)g * DIM + koff + kq);
            float s = scp ? scp[r] : 1.0f;
            uint4 u;
            u.x = f2tf32(v.x * s); u.y = f2tf32(v.y * s);
            u.z = f2tf32(v.z * s); u.w = f2tf32(v.w * s);
            *(uint4*)&As[r * AP + kq] = u;
        }
        // ---- stage B: 32 k x 128 n (straight copy of pre-converted weights)
        #pragma unroll
        for (int i = 0; i < 4; i++) {
            int idx = t + i * 256;
            int k   = idx >> 5;               // 0..31
            int n4  = (idx & 31) * 4;         // 0..124
            uint4 u = *(const uint4*)(wt + (size_t)(kb + k) * DIM + n4);
            *(uint4*)&Bs[k * BP + n4] = u;
        }
        __syncthreads();

        // ---- compute: 4 k-steps of 8
        #pragma unroll
        for (int ks = 0; ks < 4; ks++) {
            const int k0 = ks * 8;
            unsigned a[2][4];
            #pragma unroll
            for (int mt = 0; mt < 2; mt++) {
                int m = wm + mt * 16 + gid;
                a[mt][0] = As[m * AP + k0 + tig];
                a[mt][1] = As[(m + 8) * AP + k0 + tig];
                a[mt][2] = As[m * AP + k0 + tig + 4];
                a[mt][3] = As[(m + 8) * AP + k0 + tig + 4];
            }
            unsigned b[8][2];
            #pragma unroll
            for (int nt = 0; nt < 8; nt++) {
                int nn = wn + nt * 8 + gid;
                b[nt][0] = Bs[(k0 + tig) * BP + nn];
                b[nt][1] = Bs[(k0 + tig + 4) * BP + nn];
            }
            #pragma unroll
            for (int mt = 0; mt < 2; mt++)
                #pragma unroll
                for (int nt = 0; nt < 8; nt++)
                    mma_tf32(acc[mt][nt], a[mt], b[nt]);
        }
    }

    // ---- epilogue: D layout c0:(m, 2*tig) c1:(m, 2*tig+1) c2:(m+8, ..) c3
    #pragma unroll
    for (int mt = 0; mt < 2; mt++) {
        int m_lo = row0 + wm + mt * 16 + gid;
        int m_hi = m_lo + 8;
        #pragma unroll
        for (int nt = 0; nt < 8; nt++) {
            int nn = wn + nt * 8 + 2 * tig;
            float2 bv = *(float2*)&sbias[nn];
            if (m_lo < n) {
                float2 o; o.x = acc[mt][nt][0] + bv.x; o.y = acc[mt][nt][1] + bv.y;
                *(float2*)(out + (size_t)m_lo * DIM + nn) = o;
            }
            if (m_hi < n) {
                float2 o; o.x = acc[mt][nt][2] + bv.x; o.y = acc[mt][nt][3] + bv.y;
                *(float2*)(out + (size_t)m_hi * DIM + nn) = o;
            }
        }
    }
}

// ---------------- launch -----------------------------------------------------
extern "C" void kernel_launch(void* const* d_in, const int* in_sizes, int n_in,
                              void* d_out, int out_size)
{
    const float* x     = nullptr;
    const void*  ei    = nullptr;
    const float* Ws[3] = {nullptr, nullptr, nullptr};
    const float* bs[3] = {nullptr, nullptr, nullptr};
    int nw = 0, nb = 0;
    long long x_elems = 0, ei_elems = 0;

    for (int i = 0; i < n_in; i++) {
        long long sz = in_sizes[i];
        if (sz > 4000000)         { x = (const float*)d_in[i]; x_elems = sz; }
        else if (sz > 100000)     { ei = d_in[i]; ei_elems = sz; }
        else if (sz == DIM * DIM) { if (nw < 3) Ws[nw++] = (const float*)d_in[i]; }
        else if (sz == DIM)       { if (nb < 3) bs[nb++] = (const float*)d_in[i]; }
    }
    if (!x || !ei || nw < 3 || nb < 3) return;

    float* out = (float*)d_out;
    int n = (int)(x_elems / DIM);
    int e = (int)(ei_elems / 2);

    void *p_si, *p_so, *p_ci, *p_co, *p_wt;
    cudaGetSymbolAddress(&p_si, g_sum_in);
    cudaGetSymbolAddress(&p_so, g_sum_out);
    cudaGetSymbolAddress(&p_ci, g_cnt_in);
    cudaGetSymbolAddress(&p_co, g_cnt_out);
    cudaGetSymbolAddress(&p_wt, g_wt);

    cudaMemsetAsync(p_si, 0, (size_t)n * DIM * sizeof(float), 0);
    cudaMemsetAsync(p_so, 0, (size_t)n * DIM * sizeof(float), 0);
    cudaMemsetAsync(p_ci, 0, (size_t)n * sizeof(int), 0);
    cudaMemsetAsync(p_co, 0, (size_t)n * sizeof(int), 0);

    detect_kernel<<<1, 1>>>(ei, e, n);
    wt_kernel<<<(KTOT * DIM + 255) / 256, 256>>>(Ws[0], Ws[1], Ws[2], (unsigned int*)p_wt);

    int agg_blocks = (e + 7) / 8;
    agg_kernel<<<agg_blocks, 256>>>(x, ei, (float*)p_si, (float*)p_so,
                                    (int*)p_ci, (int*)p_co, e, n);

    int gemm_blocks = (n + 127) / 128;
    gemm_kernel<<<gemm_blocks, 256>>>(
        x, bs[0], bs[1], bs[2],
        (const float*)p_si, (const float*)p_so,
        (const int*)p_ci, (const int*)p_co,
        (const unsigned int*)p_wt, out, n);
}